// round 11
// baseline (speedup 1.0000x reference)
#include <cuda_runtime.h>

// N = 2,000,000 rows. Elementwise Gaussian-splat covariance projection.
// Inputs: rot (N,4) f32, mod (1,) f32, scale (N,2) f32, p_k (N,3) f32,
//         view_matrix (N,16) f32.  Output: A (N,9) f32.
//
// R6: cp.async (LDGSTS) staging of ALL inputs into smem — loads carry no
// register cost, so occupancy jumps 45% -> ~87% while keeping full MLP.
//   - every input slice is block-contiguous -> perfectly coalesced 16B cp.async
//   - vm staged at 20-word row stride -> conflict-free LDS.128 (20i mod 32 distinct)
//   - output smem aliases the rot/sc/p region (freed before output phase)
//   - coalesced float4 staged stores (proven since R2)

#define TPB 256
#define RPB 256

// smem word offsets (floats)
#define S_ROT 0                     // 256*4  = 1024 words
#define S_SC  1024                  // 256*2  =  512 words
#define S_P   1536                  // 256*3  =  768 words
#define S_VM  2304                  // 256*20 = 5120 words (16 data + 4 pad)
#define S_TOT 7424                  // 29,696 bytes
// output alias: words [0, 2304) = exactly rot+sc+p region

#define CPA16(sw_bytes, gptr) \
    asm volatile("cp.async.cg.shared.global [%0], [%1], 16;" \
                 :: "r"(sw_bytes), "l"(gptr))

__global__ __launch_bounds__(TPB)
void splat_cov_kernel(const float4* __restrict__ rot,       // (N,4)
                      const float*  __restrict__ mod,       // (1,)
                      const float2* __restrict__ scale,     // (N,2)
                      const float*  __restrict__ p_k,       // (N,3)
                      const float4* __restrict__ vm4,       // (N,16)
                      float*        __restrict__ out,       // (N,9)
                      int n)
{
    __shared__ __align__(16) float sm[S_TOT];

    const int tid = threadIdx.x;
    const int block_base = blockIdx.x * RPB;
    const int rows = min(RPB, n - block_base);

    const unsigned smb = (unsigned)__cvta_generic_to_shared(sm);

    const float* grot = (const float*)(rot + block_base);          // rows*4 floats
    const float* gsc  = (const float*)(scale + block_base);        // rows*2
    const float* gp   = p_k + (size_t)block_base * 3;              // rows*3
    const float* gvm  = (const float*)(vm4 + (size_t)block_base * 4); // rows*16

    // ---- Async-stage all inputs (16B chunks, all coalesced) ----
    {
        const int c_rot = rows;                 // rows*16B / 16
        const int c_sc  = (rows * 2) >> 2;      // rows*8B  / 16
        const int c_p   = (rows * 3) >> 2;      // rows*12B / 16
        const int c_vm  = rows * 4;             // rows*64B / 16

        for (int t = tid; t < c_vm; t += TPB) {
            int row = t >> 2, j = t & 3;
            CPA16(smb + (S_VM + row * 20 + j * 4) * 4, gvm + t * 4);
        }
        for (int t = tid; t < c_rot; t += TPB)
            CPA16(smb + (S_ROT + t * 4) * 4, grot + t * 4);
        for (int t = tid; t < c_sc; t += TPB)
            CPA16(smb + (S_SC + t * 4) * 4, gsc + t * 4);
        for (int t = tid; t < c_p; t += TPB)
            CPA16(smb + (S_P + t * 4) * 4, gp + t * 4);

        // scalar tails (only if rows % 4 != 0; never for this N, kept for safety)
        for (int t = (c_sc << 2) + tid; t < rows * 2; t += TPB)
            sm[S_SC + t] = gsc[t];
        for (int t = (c_p << 2) + tid; t < rows * 3; t += TPB)
            sm[S_P + t] = gp[t];

        asm volatile("cp.async.commit_group;");
        asm volatile("cp.async.wait_group 0;");
    }

    const float m = __ldg(mod);
    __syncthreads();   // staged data visible to all threads

    // ---- Compute (1 row/thread, all operands from smem, results in regs) ----
    float o0, o1, o2, o3, o4, o5, o6, o7, o8;
    const bool act = tid < rows;
    if (act) {
        const float4 q = *(const float4*)&sm[S_ROT + tid * 4];   // stride 4: cf-free
        const float2 sc2 = *(const float2*)&sm[S_SC + tid * 2];  // stride 2: cf-free
        const float p0 = sm[S_P + tid * 3 + 0];                  // stride 3: cf-free
        const float p1 = sm[S_P + tid * 3 + 1];
        const float p2 = sm[S_P + tid * 3 + 2];
        const float* v = &sm[S_VM + tid * 20];                   // stride 20: cf-free

        float r = q.x, x = q.y, y = q.z, z = q.w;
        float R00 = 1.0f - 2.0f * (y * y + z * z);
        float R10 = 2.0f * (x * y + r * z);
        float R20 = 2.0f * (x * z - r * y);
        float R01 = 2.0f * (x * y - r * z);
        float R11 = 1.0f - 2.0f * (x * x + z * z);
        float R21 = 2.0f * (y * z + r * x);

        float s0 = m * sc2.x, s1 = m * sc2.y;
        float u0 = s0 * R00, u1 = s0 * R10, u2 = s0 * R20;
        float v0 = s1 * R01, v1 = s1 * R11, v2 = s1 * R21;

        float m00 = v[0],  m01 = v[1],  m02 = v[2];
        float m40 = v[4],  m41 = v[5],  m42 = v[6];
        float m80 = v[8],  m81 = v[9],  m82 = v[10];
        float mc0 = v[12], mc1 = v[13], mc2 = v[14];

        o0 = m00 * u0 + m40 * u1 + m80 * u2;
        o1 = m00 * v0 + m40 * v1 + m80 * v2;
        o2 = m00 * p0 + m40 * p1 + m80 * p2 + mc0;
        o3 = m01 * u0 + m41 * u1 + m81 * u2;
        o4 = m01 * v0 + m41 * v1 + m81 * v2;
        o5 = m01 * p0 + m41 * p1 + m81 * p2 + mc1;
        o6 = m02 * u0 + m42 * u1 + m82 * u2;
        o7 = m02 * v0 + m42 * v1 + m82 * v2;
        o8 = m02 * p0 + m42 * p1 + m82 * p2 + mc2;
    }

    __syncthreads();   // all input reads done -> safe to alias output region

    if (act) {
        float* o = sm + tid * 9;    // stride 9: conflict-free, aliases rot/sc/p
        o[0] = o0; o[1] = o1; o[2] = o2;
        o[3] = o3; o[4] = o4; o[5] = o5;
        o[6] = o6; o[7] = o7; o[8] = o8;
    }

    __syncthreads();

    // ---- Store cooperatively: coalesced float4 stores ----
    {
        const int nfloat = rows * 9;                      // up to 2304
        const size_t out_base = (size_t)block_base * 9;   // 2304*blockIdx -> aligned
        float4* dst = (float4*)(out + out_base);
        const float4* src = (const float4*)sm;
        const int nvec = nfloat >> 2;                     // up to 576
        #pragma unroll 2
        for (int t = tid; t < nvec; t += TPB) dst[t] = src[t];
        for (int t = (nvec << 2) + tid; t < nfloat; t += TPB)
            out[out_base + t] = sm[t];
    }
}

extern "C" void kernel_launch(void* const* d_in, const int* in_sizes, int n_in,
                              void* d_out, int out_size)
{
    const float4* rot   = (const float4*)d_in[0];
    const float*  mod   = (const float*)d_in[1];
    const float2* scale = (const float2*)d_in[2];
    const float*  p_k   = (const float*)d_in[3];
    const float4* vm4   = (const float4*)d_in[4];
    float* out = (float*)d_out;

    int n = in_sizes[0] / 4;   // rot has N*4 elements

    int blocks = (n + RPB - 1) / RPB;
    splat_cov_kernel<<<blocks, TPB>>>(rot, mod, scale, p_k, vm4, out, n);
}

// round 12
// speedup vs baseline: 1.0007x; 1.0007x over previous
#include <cuda_runtime.h>

// N = 2,000,000 rows. Elementwise Gaussian-splat covariance projection.
// Inputs: rot (N,4) f32, mod (1,) f32, scale (N,2) f32, p_k (N,3) f32,
//         view_matrix (N,16) f32.  Output: A (N,9) f32.
//
// R7 hybrid (from R5/R6 post-mortems):
//   - vm  (64B/row): cp.async -> smem @ stride-20 rows (no reg cost, cf-free LDS)
//   - p_k (12B/row): cp.async -> smem (coalesced 16B chunks)
//   - rot/scale (24B/row): per-thread direct LDG.128/LDG.64 (wavefront-optimal,
//     only ~6 regs) issued while cp.async is in flight
//   - output: regs -> smem (aliases vm region) -> coalesced float4 stores
//   - low regs + 23.5 KB smem -> ~8 CTAs/SM

#define TPB 256
#define RPB 256

// smem word offsets (floats)
#define S_VM  0                     // 256 rows * 20 words (16 data + 4 pad) = 5120
#define S_P   5120                  // 256*3 = 768
#define S_TOT 5888                  // 23,552 bytes
// output (2304 words) aliases S_VM region after vm reads complete

#define CPA16(sw_bytes, gptr) \
    asm volatile("cp.async.cg.shared.global [%0], [%1], 16;" \
                 :: "r"(sw_bytes), "l"(gptr))

__global__ __launch_bounds__(TPB)
void splat_cov_kernel(const float4* __restrict__ rot,       // (N,4)
                      const float*  __restrict__ mod,       // (1,)
                      const float2* __restrict__ scale,     // (N,2)
                      const float*  __restrict__ p_k,       // (N,3)
                      const float4* __restrict__ vm4,       // (N,16)
                      float*        __restrict__ out,       // (N,9)
                      int n)
{
    __shared__ __align__(16) float sm[S_TOT];

    const int tid = threadIdx.x;
    const int block_base = blockIdx.x * RPB;
    const int rows = min(RPB, n - block_base);

    const unsigned smb = (unsigned)__cvta_generic_to_shared(sm);

    const float* gp  = p_k + (size_t)block_base * 3;                  // rows*3 floats
    const float* gvm = (const float*)(vm4 + (size_t)block_base * 4);  // rows*16

    // ---- cp.async: vm (4 chunks/thread) + p_k (<=1 chunk/thread) ----
    {
        const int c_vm = rows * 4;              // 16B chunks
        #pragma unroll 4
        for (int t = tid; t < c_vm; t += TPB) {
            int row = t >> 2, j = t & 3;
            CPA16(smb + (S_VM + row * 20 + j * 4) * 4, gvm + t * 4);
        }
        const int c_p = (rows * 3) >> 2;
        for (int t = tid; t < c_p; t += TPB)
            CPA16(smb + (S_P + t * 4) * 4, gp + t * 4);
        for (int t = (c_p << 2) + tid; t < rows * 3; t += TPB)  // tail (never for this N)
            sm[S_P + t] = gp[t];
        asm volatile("cp.async.commit_group;");
    }

    // ---- Per-thread direct loads overlap with cp.async in flight ----
    const float m = __ldg(mod);
    const int i = block_base + tid;
    const bool act = i < n;
    float4 q = make_float4(0.f, 0.f, 0.f, 0.f);
    float2 sc2 = make_float2(0.f, 0.f);
    if (act) {
        q   = rot[i];       // stride-16B across warp: wavefront-optimal
        sc2 = scale[i];     // stride-8B: wavefront-optimal
    }

    asm volatile("cp.async.wait_group 0;");
    __syncthreads();

    // ---- Compute (operands: regs + smem), results kept in regs ----
    float o0, o1, o2, o3, o4, o5, o6, o7, o8;
    if (act) {
        float r = q.x, x = q.y, y = q.z, z = q.w;
        float R00 = 1.0f - 2.0f * (y * y + z * z);
        float R10 = 2.0f * (x * y + r * z);
        float R20 = 2.0f * (x * z - r * y);
        float R01 = 2.0f * (x * y - r * z);
        float R11 = 1.0f - 2.0f * (x * x + z * z);
        float R21 = 2.0f * (y * z + r * x);

        float s0 = m * sc2.x, s1 = m * sc2.y;
        float u0 = s0 * R00, u1 = s0 * R10, u2 = s0 * R20;
        float v0 = s1 * R01, v1 = s1 * R11, v2 = s1 * R21;

        const float* v = &sm[S_VM + tid * 20];   // stride 20 -> conflict-free
        float m00 = v[0],  m01 = v[1],  m02 = v[2];
        float m40 = v[4],  m41 = v[5],  m42 = v[6];
        float m80 = v[8],  m81 = v[9],  m82 = v[10];
        float mc0 = v[12], mc1 = v[13], mc2 = v[14];

        float p0 = sm[S_P + tid * 3 + 0];        // stride 3 -> conflict-free
        float p1 = sm[S_P + tid * 3 + 1];
        float p2 = sm[S_P + tid * 3 + 2];

        o0 = m00 * u0 + m40 * u1 + m80 * u2;
        o1 = m00 * v0 + m40 * v1 + m80 * v2;
        o2 = m00 * p0 + m40 * p1 + m80 * p2 + mc0;
        o3 = m01 * u0 + m41 * u1 + m81 * u2;
        o4 = m01 * v0 + m41 * v1 + m81 * v2;
        o5 = m01 * p0 + m41 * p1 + m81 * p2 + mc1;
        o6 = m02 * u0 + m42 * u1 + m82 * u2;
        o7 = m02 * v0 + m42 * v1 + m82 * v2;
        o8 = m02 * p0 + m42 * p1 + m82 * p2 + mc2;
    }

    __syncthreads();   // vm reads done -> safe to alias output over S_VM

    if (act) {
        float* o = sm + tid * 9;   // stride 9 -> conflict-free; aliases vm region
        o[0] = o0; o[1] = o1; o[2] = o2;
        o[3] = o3; o[4] = o4; o[5] = o5;
        o[6] = o6; o[7] = o7; o[8] = o8;
    }

    __syncthreads();

    // ---- Store cooperatively: coalesced float4 stores ----
    {
        const int nfloat = rows * 9;                      // up to 2304
        const size_t out_base = (size_t)block_base * 9;   // 2304*blockIdx -> aligned
        float4* dst = (float4*)(out + out_base);
        const float4* src = (const float4*)sm;
        const int nvec = nfloat >> 2;                     // up to 576
        #pragma unroll 2
        for (int t = tid; t < nvec; t += TPB) dst[t] = src[t];
        for (int t = (nvec << 2) + tid; t < nfloat; t += TPB)
            out[out_base + t] = sm[t];
    }
}

extern "C" void kernel_launch(void* const* d_in, const int* in_sizes, int n_in,
                              void* d_out, int out_size)
{
    const float4* rot   = (const float4*)d_in[0];
    const float*  mod   = (const float*)d_in[1];
    const float2* scale = (const float2*)d_in[2];
    const float*  p_k   = (const float*)d_in[3];
    const float4* vm4   = (const float4*)d_in[4];
    float* out = (float*)d_out;

    int n = in_sizes[0] / 4;   // rot has N*4 elements

    int blocks = (n + RPB - 1) / RPB;
    splat_cov_kernel<<<blocks, TPB>>>(rot, mod, scale, p_k, vm4, out, n);
}

// round 15
// speedup vs baseline: 1.0471x; 1.0463x over previous
#include <cuda_runtime.h>

// N = 2,000,000 rows. Elementwise Gaussian-splat covariance projection.
// Inputs: rot (N,4) f32, mod (1,) f32, scale (N,2) f32, p_k (N,3) f32,
//         view_matrix (N,16) f32.  Output: A (N,9) f32.
//
// R8 = champion R5 minus overhead:
//   - TPB=128, RPT=2; ALL inputs front-batched per-thread direct LDGs
//     (q: LDG.128, sc: LDG.64, vm: 4x LDG.128, p_k: 3x LDG.32) -> max MLP
//   - p_k smem staging DELETED (L1 has headroom; saves loops + one barrier)
//   - output staged via smem -> coalesced float4 stores (proven since R2)
//   - no cp.async (loses ~1.5us on bench vs direct LDG), no reg caps,
//     no cache hints (all tested, all neutral-to-negative)

#define TPB 128
#define RPT 2
#define RPB (TPB * RPT)             // 256 rows per block

__global__ __launch_bounds__(TPB)
void splat_cov_kernel(const float4* __restrict__ rot,       // (N,4) as float4
                      const float*  __restrict__ mod,       // (1,)
                      const float2* __restrict__ scale,     // (N,2) as float2
                      const float*  __restrict__ p_k,       // (N,3)
                      const float4* __restrict__ vm4,       // (N,16) as 4x float4
                      float*        __restrict__ out,       // (N,9)
                      int n)
{
    __shared__ float s_o[RPB * 9];   // 9 KB staged output

    const int tid = threadIdx.x;
    const int block_base = blockIdx.x * RPB;
    const int rows = min(RPB, n - block_base);

    const float m = __ldg(mod);

    int idx[RPT];
    bool act[RPT];
    #pragma unroll
    for (int k = 0; k < RPT; k++) {
        idx[k] = block_base + tid + k * TPB;
        act[k] = idx[k] < n;
    }

    // ---- Front-batch ALL global loads (18 LDGs in flight per thread) ----
    float4 q[RPT];
    float2 sc[RPT];
    float4 c0[RPT], c1[RPT], c2[RPT], c3[RPT];
    float  p0[RPT], p1[RPT], p2[RPT];
    #pragma unroll
    for (int k = 0; k < RPT; k++) {
        if (act[k]) {
            q[k]  = rot[idx[k]];
            sc[k] = scale[idx[k]];
            const float4* v = vm4 + (size_t)idx[k] * 4;
            c0[k] = v[0]; c1[k] = v[1]; c2[k] = v[2]; c3[k] = v[3];
            const float* p = p_k + (size_t)idx[k] * 3;
            p0[k] = p[0]; p1[k] = p[1]; p2[k] = p[2];
        }
    }

    #pragma unroll
    for (int k = 0; k < RPT; k++) {
        if (!act[k]) continue;

        float r = q[k].x, x = q[k].y, y = q[k].z, z = q[k].w;

        float R00 = 1.0f - 2.0f * (y * y + z * z);
        float R10 = 2.0f * (x * y + r * z);
        float R20 = 2.0f * (x * z - r * y);
        float R01 = 2.0f * (x * y - r * z);
        float R11 = 1.0f - 2.0f * (x * x + z * z);
        float R21 = 2.0f * (y * z + r * x);

        float s0 = m * sc[k].x;
        float s1 = m * sc[k].y;

        float u0 = s0 * R00, u1 = s0 * R10, u2 = s0 * R20;
        float v0 = s1 * R01, v1 = s1 * R11, v2 = s1 * R21;

        const int lrow = tid + k * TPB;                    // local row in block
        float* o = s_o + lrow * 9;                         // odd stride: conflict-free
        o[0] = c0[k].x * u0 + c1[k].x * u1 + c2[k].x * u2;
        o[1] = c0[k].x * v0 + c1[k].x * v1 + c2[k].x * v2;
        o[2] = c0[k].x * p0[k] + c1[k].x * p1[k] + c2[k].x * p2[k] + c3[k].x;
        o[3] = c0[k].y * u0 + c1[k].y * u1 + c2[k].y * u2;
        o[4] = c0[k].y * v0 + c1[k].y * v1 + c2[k].y * v2;
        o[5] = c0[k].y * p0[k] + c1[k].y * p1[k] + c2[k].y * p2[k] + c3[k].y;
        o[6] = c0[k].z * u0 + c1[k].z * u1 + c2[k].z * u2;
        o[7] = c0[k].z * v0 + c1[k].z * v1 + c2[k].z * v2;
        o[8] = c0[k].z * p0[k] + c1[k].z * p1[k] + c2[k].z * p2[k] + c3[k].z;
    }

    __syncthreads();   // outputs staged

    // ---- Store cooperatively: coalesced float4 stores ----
    {
        const int nfloat = rows * 9;                       // up to 2304
        const size_t out_base = (size_t)block_base * 9;    // 2304*blockIdx -> aligned
        float4* dst = (float4*)(out + out_base);
        const float4* src = (const float4*)s_o;
        const int nvec = nfloat >> 2;                      // up to 576
        #pragma unroll 4
        for (int t = tid; t < nvec; t += TPB) dst[t] = src[t];
        for (int t = (nvec << 2) + tid; t < nfloat; t += TPB)
            out[out_base + t] = s_o[t];
    }
}

extern "C" void kernel_launch(void* const* d_in, const int* in_sizes, int n_in,
                              void* d_out, int out_size)
{
    const float4* rot   = (const float4*)d_in[0];
    const float*  mod   = (const float*)d_in[1];
    const float2* scale = (const float2*)d_in[2];
    const float*  p_k   = (const float*)d_in[3];
    const float4* vm4   = (const float4*)d_in[4];
    float* out = (float*)d_out;

    int n = in_sizes[0] / 4;   // rot has N*4 elements

    int blocks = (n + RPB - 1) / RPB;
    splat_cov_kernel<<<blocks, TPB>>>(rot, mod, scale, p_k, vm4, out, n);
}